// round 17
// baseline (speedup 1.0000x reference)
#include <cuda_runtime.h>
#include <cuda_bf16.h>

#define N_SRC_C   100000
#define N_DST_C   50000
#define N_EDGES_C 800000
#define DD        64

// W transposed: Wt[k*64 + j] = W[j*128 + k]
__device__ float g_Wt[128 * 64];
// rowptr[r] = first edge index e with dst_idx[e] >= r;  rowptr[N_DST] = N_EDGES
__device__ int g_rowptr[N_DST_C + 1];

// Packed f32x2 helpers (sm_103a)
#define FMA2(d, a, bb) \
    asm("fma.rn.f32x2 %0, %1, %2, %3;" : "=l"(d) : "l"(a), "l"(bb), "l"(d))
#define PACKDUP(o, x) \
    asm("mov.b64 %0, {%1, %1};" : "=l"(o) : "f"(x))

// ---------------------------------------------------------------------------
// Kernel 1: W transpose + rowptr scatter.  Each thread handles 4 edges via
// one int4 load (sorted dst_idx; boundary threads fill the gap rows).
// ---------------------------------------------------------------------------
__global__ void prep_kernel(const float* __restrict__ W,
                            const int*   __restrict__ dst_idx) {
    int i = blockIdx.x * blockDim.x + threadIdx.x;
    if (i < 128 * 64) {
        int jj = i >> 7;        // W row  (0..63)
        int k  = i & 127;       // W col  (0..127)
        g_Wt[k * 64 + jj] = __ldg(W + i);
    }
    int e0 = i * 4;
    if (e0 < N_EDGES_C) {
        int4 d4 = __ldg((const int4*)(dst_idx + e0));
        int dprev = (e0 == 0) ? -1 : __ldg(dst_idx + e0 - 1);
        int dd[4] = { d4.x, d4.y, d4.z, d4.w };
        #pragma unroll
        for (int j = 0; j < 4; j++) {
            for (int r = dprev + 1; r <= dd[j]; r++)
                g_rowptr[r] = e0 + j;
            dprev = dd[j];
        }
        if (e0 + 4 >= N_EDGES_C)
            for (int r = dprev + 1; r <= N_DST_C; r++)
                g_rowptr[r] = N_EDGES_C;
    }
}

// ---------------------------------------------------------------------------
// Kernel 2 (fused agg + neigh + gemm). One block = 64 dst rows.
// Phase 1: 16-lane groups gather 4 rows each; y = 0.9*HBar + 0.1*mean is
//          written to out2 (global, coalesced) AND staged in smem ybuf.
// Phase 2: the measured 4x4 f32x2 gemm; second k-half reads y from ybuf
//          (16-lane broadcast LDS) instead of global.
// smem = 32KB W + 16KB ybuf = 48KB -> 4 blocks/SM.
// ---------------------------------------------------------------------------
__global__ void __launch_bounds__(256, 4)
fused_kernel(const float* __restrict__ H_src,
             const int*   __restrict__ src_idx,
             const float* __restrict__ H_dst,
             const float* __restrict__ HBar,
             const float* __restrict__ b,
             float* __restrict__ out,
             float* __restrict__ out2) {
    __shared__ float ws[128 * 64];     // 32 KB
    __shared__ float ybuf[64 * 64];    // 16 KB

    int t = threadIdx.x;
    // Load W tile (conflict-free linear float4 copy)
    #pragma unroll
    for (int i = 0; i < 8; i++) {
        int idx = t + i * 256;
        reinterpret_cast<float4*>(ws)[idx] =
            __ldg(reinterpret_cast<const float4*>(g_Wt) + idx);
    }

    // ---- Phase 1: gather + neigh ----
    {
        int lane = t & 15;                   // float4 column index
        int grp  = t >> 4;                   // 0..15
        unsigned gmask = 0xFFFFu << (t & 16);

        #pragma unroll 1
        for (int it = 0; it < 4; it++) {
            int rl = grp * 4 + it;           // local row 0..63
            int r  = blockIdx.x * 64 + rl;
            float4 o = make_float4(0.f, 0.f, 0.f, 0.f);
            if (r < N_DST_C) {
                int lo = __ldg(g_rowptr + r);
                int hi = __ldg(g_rowptr + r + 1);
                int deg = hi - lo;
                float4 acc = make_float4(0.f, 0.f, 0.f, 0.f);
                for (int base = lo; base < hi; base += 16) {
                    int e = base + lane;
                    int sidx = (e < hi) ? __ldg(src_idx + e) : 0;
                    int cnt = hi - base;
                    if (cnt >= 16) {
                        #pragma unroll
                        for (int j = 0; j < 16; j++) {
                            int s = __shfl_sync(gmask, sidx, j, 16);
                            float4 v = __ldg((const float4*)(H_src + (size_t)s * DD) + lane);
                            acc.x += v.x; acc.y += v.y; acc.z += v.z; acc.w += v.w;
                        }
                    } else {
                        for (int j = 0; j < cnt; j++) {
                            int s = __shfl_sync(gmask, sidx, j, 16);
                            float4 v = __ldg((const float4*)(H_src + (size_t)s * DD) + lane);
                            acc.x += v.x; acc.y += v.y; acc.z += v.z; acc.w += v.w;
                        }
                    }
                }
                float inv = 0.1f / fmaxf((float)deg, 1.f);
                float4 hb = __ldg((const float4*)(HBar + (size_t)r * DD) + lane);
                o.x = 0.9f * hb.x + inv * acc.x;
                o.y = 0.9f * hb.y + inv * acc.y;
                o.z = 0.9f * hb.z + inv * acc.z;
                o.w = 0.9f * hb.w + inv * acc.w;
                reinterpret_cast<float4*>(out2 + (size_t)r * DD)[lane] = o;
            }
            reinterpret_cast<float4*>(ybuf + rl * 64)[lane] = o;
        }
    }
    __syncthreads();

    // ---- Phase 2: gemm ----
    int tx = t & 15;
    int ty = t >> 4;
    int j0 = tx * 4;
    int r0 = (blockIdx.x << 6) + ty * 4;

    const float* xr[4];
    #pragma unroll
    for (int m = 0; m < 4; m++) {
        int row = min(r0 + m, N_DST_C - 1);
        xr[m] = H_dst + (size_t)row * DD;
    }

    unsigned long long acc[4][2];
    #pragma unroll
    for (int r = 0; r < 4; r++) { acc[r][0] = 0ull; acc[r][1] = 0ull; }

    // First half: k = 0..63 over H_dst (global LDG.128)
    #pragma unroll 4
    for (int k = 0; k < 64; k += 4) {
        float4 xa[4];
        #pragma unroll
        for (int m = 0; m < 4; m++)
            xa[m] = __ldg((const float4*)(xr[m] + k));
        #pragma unroll
        for (int kk = 0; kk < 4; kk++) {
            ulonglong2 w2 = *reinterpret_cast<const ulonglong2*>(
                ws + (k + kk) * 64 + j0);
            #pragma unroll
            for (int r = 0; r < 4; r++) {
                float xs = reinterpret_cast<const float*>(&xa[r])[kk];
                unsigned long long xx;
                PACKDUP(xx, xs);
                FMA2(acc[r][0], xx, w2.x);
                FMA2(acc[r][1], xx, w2.y);
            }
        }
    }
    // Second half: k = 64..127 over y (smem ybuf, broadcast LDS.128)
    #pragma unroll 4
    for (int k = 0; k < 64; k += 4) {
        float4 xa[4];
        #pragma unroll
        for (int m = 0; m < 4; m++)
            xa[m] = *reinterpret_cast<const float4*>(ybuf + (ty * 4 + m) * 64 + k);
        #pragma unroll
        for (int kk = 0; kk < 4; kk++) {
            ulonglong2 w2 = *reinterpret_cast<const ulonglong2*>(
                ws + (k + 64 + kk) * 64 + j0);
            #pragma unroll
            for (int r = 0; r < 4; r++) {
                float xs = reinterpret_cast<const float*>(&xa[r])[kk];
                unsigned long long xx;
                PACKDUP(xx, xs);
                FMA2(acc[r][0], xx, w2.x);
                FMA2(acc[r][1], xx, w2.y);
            }
        }
    }

    float bb[4];
    #pragma unroll
    for (int j = 0; j < 4; j++) bb[j] = __ldg(b + j0 + j);

    #pragma unroll
    for (int m = 0; m < 4; m++) {
        int row = r0 + m;
        if (row < N_DST_C) {
            float2 p0 = *reinterpret_cast<float2*>(&acc[m][0]);
            float2 p1 = *reinterpret_cast<float2*>(&acc[m][1]);
            float4 o;
            o.x = fmaxf(p0.x + bb[0], 0.f);
            o.y = fmaxf(p0.y + bb[1], 0.f);
            o.z = fmaxf(p1.x + bb[2], 0.f);
            o.w = fmaxf(p1.y + bb[3], 0.f);
            *reinterpret_cast<float4*>(out + (size_t)row * DD + j0) = o;
        }
    }
}

// ---------------------------------------------------------------------------
// Launch
// ---------------------------------------------------------------------------
extern "C" void kernel_launch(void* const* d_in, const int* in_sizes, int n_in,
                              void* d_out, int out_size) {
    const float* H_src   = (const float*)d_in[0];
    const float* H_dst   = (const float*)d_in[1];
    const float* HBar    = (const float*)d_in[2];
    const int*   src_idx = (const int*)  d_in[3];
    const int*   dst_idx = (const int*)  d_in[4];
    const float* W       = (const float*)d_in[5];
    const float* b       = (const float*)d_in[6];

    float* out  = (float*)d_out;                    // h:       [N_DST, 64]
    float* out2 = out + (size_t)N_DST_C * DD;       // h_neigh: [N_DST, 64]

    prep_kernel<<<(N_EDGES_C / 4 + 255) / 256, 256>>>(W, dst_idx);
    fused_kernel<<<(N_DST_C + 63) / 64, 256>>>(H_src, src_idx, H_dst, HBar,
                                               b, out, out2);
}